// round 15
// baseline (speedup 1.0000x reference)
#include <cuda_runtime.h>
#include <math.h>

#define NA     4096
#define NWORDS 16384
#define DIM    128
#define NZCAP  256
#define CK     23

// ------------------------- scratch (no allocations allowed) -------------------------
__device__ float g_xs[NA * DIM];
__device__ float g_hs[NA * DIM];
__device__ int   g_nzidx[NA * NZCAP];
__device__ int   g_nzcnt[NA];
__device__ float g_imgA[NWORDS * DIM];
__device__ float g_imgB[NWORDS * DIM];
__device__ float g_hsatt[NWORDS * DIM];
__device__ float g_part[256 * DIM];
__device__ float g_compound[DIM];
__device__ float g_hatt[DIM];

// ------------------------- f32x2 helpers -------------------------
typedef unsigned long long u64;
__device__ __forceinline__ void ffma2(u64& d, u64 a, u64 b) {
    asm("fma.rn.f32x2 %0, %1, %2, %0;" : "+l"(d) : "l"(a), "l"(b));
}
__device__ __forceinline__ u64 dup2(float w) {
    u64 r;
    asm("mov.b64 %0, {%1, %1};" : "=l"(r) : "r"(__float_as_uint(w)));
    return r;
}
__device__ __forceinline__ float lo32(u64 v) {
    return __uint_as_float((unsigned)(v & 0xffffffffull));
}
__device__ __forceinline__ float hi32(u64 v) {
    return __uint_as_float((unsigned)(v >> 32));
}

// ------------------------- sparse adjacency build (deterministic, ordered) -------------------------
__global__ void __launch_bounds__(256) build_nz(const float* __restrict__ adj) {
    int warp = (blockIdx.x * blockDim.x + threadIdx.x) >> 5;
    int lane = threadIdx.x & 31;
    if (warp >= NA) return;
    const float* row = adj + (size_t)warp * NA;
    int base = 0;
    for (int j0 = 0; j0 < NA; j0 += 32) {
        float v = row[j0 + lane];
        unsigned mask = __ballot_sync(0xffffffffu, v != 0.f);
        if (v != 0.f) {
            int r = __popc(mask & ((1u << lane) - 1));
            int p = base + r;
            if (p < NZCAP) g_nzidx[warp * NZCAP + p] = j0 + lane;
        }
        base += __popc(mask);
    }
    if (lane == 0) g_nzcnt[warp] = base < NZCAP ? base : NZCAP;
}

// ------------------------- GNN linear, occupancy-transparent (8.4KB smem, 128 thr) -------------------------
// Co-resides with 7 conv CTAs/SM (smem gap 11KB, reg gap ~8.5K, warp gap 36).
// W streamed from L2 (64KB, fully cached). Warp w -> output cols w*32..w*32+31.
__global__ void __launch_bounds__(128) gnn_linear_light(const float* __restrict__ X,
                                                        const float* __restrict__ W,
                                                        const float* __restrict__ b,
                                                        float* __restrict__ Y,
                                                        const int* __restrict__ gidx,
                                                        const float* __restrict__ gemb,
                                                        float* __restrict__ Xout) {
    __shared__ float sX[16][132];
    int tid = threadIdx.x;
    int r0  = blockIdx.x * 16;
    for (int idx = tid; idx < 16 * 128; idx += 128) {
        int r = idx >> 7, c = idx & 127;
        float v;
        if (gidx) {
            v = gemb[(size_t)gidx[r0 + r] * DIM + c];
            Xout[(size_t)(r0 + r) * DIM + c] = v;
        } else {
            v = X[(size_t)(r0 + r) * DIM + c];
        }
        sX[r][c] = v;
    }
    __syncthreads();

    int w = tid >> 5, lane = tid & 31;
#pragma unroll 1
    for (int jj = 0; jj < 32; ++jj) {
        int j = w * 32 + jj;
        float4 wv = *reinterpret_cast<const float4*>(W + (size_t)j * 128 + lane * 4);
        float p[16];
#pragma unroll
        for (int r = 0; r < 16; ++r) {
            float4 xv = *reinterpret_cast<const float4*>(&sX[r][lane * 4]);
            p[r] = wv.x * xv.x + wv.y * xv.y + wv.z * xv.z + wv.w * xv.w;
        }
#pragma unroll
        for (int r = 0; r < 16; ++r) {
#pragma unroll
            for (int off = 16; off; off >>= 1)
                p[r] += __shfl_xor_sync(0xffffffffu, p[r], off);
        }
        if (lane < 16) {
            float v = p[lane] + b[j];
            Y[(size_t)(r0 + lane) * DIM + j] = v > 0.f ? v : 0.f;
        }
    }
}

// ------------------------- Y = relu(X @ W^T + b), 32 rows x 64 cols, f32x2 (attlin only) -------------------------
__global__ void __launch_bounds__(256) linear_relu(const float* __restrict__ X,
                                                   const float* __restrict__ W,
                                                   const float* __restrict__ b,
                                                   float* __restrict__ Y) {
    extern __shared__ float sm[];
    float*  sW  = sm;                         // [64][129]
    float2* sXP = (float2*)(sm + 64 * 129);   // [16][128] row pairs
    int tid = threadIdx.x;
    int jh  = blockIdx.y;
    int r0  = blockIdx.x * 32;

    for (int idx = tid; idx < 64 * 128; idx += 256) {
        int j = idx >> 7, k = idx & 127;
        sW[j * 129 + k] = W[(size_t)(jh * 64 + j) * 128 + k];
    }
    for (int idx = tid; idx < 16 * 128; idx += 256) {
        int p = idx >> 7, k = idx & 127;
        int row0 = r0 + 2 * p;
        sXP[p * 128 + k] = make_float2(X[(size_t)row0 * DIM + k],
                                       X[(size_t)(row0 + 1) * DIM + k]);
    }
    __syncthreads();

    int lane = tid & 31;
    int rg   = tid >> 5;
    int i0   = rg * 4;
    const u64* sxp = reinterpret_cast<const u64*>(sXP);
    const u64* pA  = sxp + (rg * 2) * 128;
    const u64* pB  = sxp + (rg * 2 + 1) * 128;

    u64 accA[2], accB[2];
#pragma unroll
    for (int q = 0; q < 2; ++q) { accA[q] = 0ull; accB[q] = 0ull; }

#pragma unroll 4
    for (int k = 0; k < 128; ++k) {
        u64 a01 = pA[k];
        u64 a23 = pB[k];
#pragma unroll
        for (int q = 0; q < 2; ++q) {
            u64 ww = dup2(sW[(lane + q * 32) * 129 + k]);
            ffma2(accA[q], a01, ww);
            ffma2(accB[q], a23, ww);
        }
    }
#pragma unroll
    for (int q = 0; q < 2; ++q) {
        int j = jh * 64 + lane + q * 32;
        float bj = b[j];
        float v0 = lo32(accA[q]) + bj;
        float v1 = hi32(accA[q]) + bj;
        float v2 = lo32(accB[q]) + bj;
        float v3 = hi32(accB[q]) + bj;
        Y[(size_t)(r0 + i0 + 0) * DIM + j] = v0 > 0.f ? v0 : 0.f;
        Y[(size_t)(r0 + i0 + 1) * DIM + j] = v1 > 0.f ? v1 : 0.f;
        Y[(size_t)(r0 + i0 + 2) * DIM + j] = v2 > 0.f ? v2 : 0.f;
        Y[(size_t)(r0 + i0 + 3) * DIM + j] = v3 > 0.f ? v3 : 0.f;
    }
}

// ------------------------- xs += A_sparse @ hs (warp-per-row, float4 lanes) -------------------------
__global__ void __launch_bounds__(256) spmm_add(const float* __restrict__ hs) {
    int row  = blockIdx.x * 8 + (threadIdx.x >> 5);
    int lane = threadIdx.x & 31;
    int cnt = g_nzcnt[row];
    const int* nz = g_nzidx + row * NZCAP;

    float4 a0 = make_float4(0.f, 0.f, 0.f, 0.f);
    float4 a1 = make_float4(0.f, 0.f, 0.f, 0.f);
    int t = 0;
    for (; t + 2 <= cnt; t += 2) {
        int j0 = nz[t], j1 = nz[t + 1];
        float4 v0 = *reinterpret_cast<const float4*>(hs + (size_t)j0 * DIM + lane * 4);
        float4 v1 = *reinterpret_cast<const float4*>(hs + (size_t)j1 * DIM + lane * 4);
        a0.x += v0.x; a0.y += v0.y; a0.z += v0.z; a0.w += v0.w;
        a1.x += v1.x; a1.y += v1.y; a1.z += v1.z; a1.w += v1.w;
    }
    if (t < cnt) {
        float4 v0 = *reinterpret_cast<const float4*>(hs + (size_t)nz[t] * DIM + lane * 4);
        a0.x += v0.x; a0.y += v0.y; a0.z += v0.z; a0.w += v0.w;
    }
    float4* dst = reinterpret_cast<float4*>(g_xs + (size_t)row * DIM + lane * 4);
    float4 x = *dst;
    x.x += a0.x + a1.x;
    x.y += a0.y + a1.y;
    x.z += a0.z + a1.z;
    x.w += a0.w + a1.w;
    *dst = x;
}

// ------------------------- column-sum partials -------------------------
__global__ void colsum_partial(const float* __restrict__ X, float* __restrict__ part,
                               int rows_per_block) {
    int c = threadIdx.x;
    int r0 = blockIdx.x * rows_per_block;
    float acc = 0.f;
    for (int r = 0; r < rows_per_block; ++r) acc += X[(size_t)(r0 + r) * DIM + c];
    part[blockIdx.x * DIM + c] = acc;
}

// ------------------------- 23x23 SAME conv + bias + leaky_relu (proven 8-row body) -------------------------
#define SPITCH 88
#define TROWS  38   // 16 + 22 halo
__global__ void __launch_bounds__(128) conv_leaky(const float* __restrict__ in,
                                                  float* __restrict__ out,
                                                  const float* __restrict__ kw,
                                                  const float* __restrict__ kb,
                                                  const int* __restrict__ widx,
                                                  const float* __restrict__ wemb) {
    __shared__ float2 s_in2[TROWS * SPITCH];
    __shared__ float2 s_k2[CK * CK];
    int tid = threadIdx.x + threadIdx.y * 64;
    int r0  = blockIdx.x * 16;

    for (int idx = tid; idx < TROWS * 86; idx += 128) {
        int rr = idx / 86;
        int qi = idx - rr * 86;
        int gr = r0 - 11 + rr;
        int q  = qi - 11;
        float lo = 0.f, hi = 0.f;
        if (gr >= 0 && gr < NWORDS) {
            const float* grow = widx ? (wemb + (size_t)widx[gr] * DIM)
                                     : (in + (size_t)gr * DIM);
            if (q >= 0)       lo = grow[q];
            if (q + 64 < 128) hi = grow[q + 64];
        }
        s_in2[rr * SPITCH + qi] = make_float2(lo, hi);
    }
    for (int idx = tid; idx < CK * CK; idx += 128) {
        float w = kw[idx];
        s_k2[idx] = make_float2(w, w);
    }
    __syncthreads();

    float bias = kb[0];
    int cp    = threadIdx.x;
    int rbase = threadIdx.y * 8;

    u64 acc2[8];
#pragma unroll
    for (int o = 0; o < 8; ++o) acc2[o] = 0ull;

#pragma unroll 1
    for (int dc = 0; dc < CK; ++dc) {
        u64 wc2[CK];
#pragma unroll
        for (int dr = 0; dr < CK; ++dr)
            wc2[dr] = *reinterpret_cast<const u64*>(&s_k2[dr * CK + dc]);

        const u64* col = reinterpret_cast<const u64*>(s_in2) + rbase * SPITCH + cp + dc;
#pragma unroll
        for (int R = 0; R < 30; ++R) {
            u64 v2 = col[R * SPITCH];
#pragma unroll
            for (int dr = 0; dr < CK; ++dr) {
                int o = R - dr;
                if (o >= 0 && o < 8) ffma2(acc2[o], v2, wc2[dr]);
            }
        }
    }

#pragma unroll
    for (int o = 0; o < 8; ++o) {
        int row = r0 + rbase + o;
        float vl = lo32(acc2[o]) + bias;
        float vh = hi32(acc2[o]) + bias;
        out[(size_t)row * DIM + cp]      = vl > 0.f ? vl : 0.01f * vl;
        out[(size_t)row * DIM + cp + 64] = vh > 0.f ? vh : 0.01f * vh;
    }
}

// ------------------------- fused: GNN combine -> compound -> h_att -------------------------
__global__ void comb_att(const float* __restrict__ part, const float* __restrict__ W,
                         const float* __restrict__ b) {
    __shared__ float sc[DIM];
    int j = threadIdx.x;   // 128
    float acc = 0.f;
    for (int i = 0; i < 32; ++i) acc += part[i * DIM + j];
    float compv = acc * (1.0f / NA);
    g_compound[j] = compv;
    sc[j] = compv;
    __syncthreads();
    float h = b[j];
    for (int k = 0; k < 128; ++k) h += sc[k] * W[j * DIM + k];
    g_hatt[j] = h > 0.f ? h : 0.f;
}

// ------------------------- protein attention partials (grid 256, 64 rows/block) -------------------------
__global__ void protein_partial(const float* __restrict__ hs) {
    __shared__ float sh[DIM];
    __shared__ float sacc[4][DIM];
    int tid  = threadIdx.x;
    int lane = tid & 31;
    int w    = tid >> 5;
    sh[tid] = g_hatt[tid];
    __syncthreads();
    float h0 = sh[lane], h1 = sh[lane + 32], h2 = sh[lane + 64], h3 = sh[lane + 96];
    float a0 = 0.f, a1 = 0.f, a2 = 0.f, a3 = 0.f;
    int m0 = blockIdx.x * 64 + w * 16;
    for (int mi = 0; mi < 16; ++mi) {
        const float* row = hs + (size_t)(m0 + mi) * DIM;
        float d = row[lane] * h0 + row[lane + 32] * h1 + row[lane + 64] * h2 + row[lane + 96] * h3;
#pragma unroll
        for (int off = 16; off; off >>= 1) d += __shfl_xor_sync(0xffffffffu, d, off);
        float t = tanhf(d);
        float4 v = *reinterpret_cast<const float4*>(row + lane * 4);
        a0 += t * v.x;
        a1 += t * v.y;
        a2 += t * v.z;
        a3 += t * v.w;
    }
    sacc[w][lane * 4 + 0] = a0;
    sacc[w][lane * 4 + 1] = a1;
    sacc[w][lane * 4 + 2] = a2;
    sacc[w][lane * 4 + 3] = a3;
    __syncthreads();
    g_part[blockIdx.x * DIM + tid] =
        (sacc[0][tid] + sacc[1][tid]) + (sacc[2][tid] + sacc[3][tid]);
}

// ------------------------- fused: protein combine + 2-layer MLP + scalar head -------------------------
__global__ void final_mlp(const float* __restrict__ part,
                          const float* __restrict__ Wout, const float* __restrict__ bout,
                          const float* __restrict__ Wint, const float* __restrict__ bint,
                          float* __restrict__ out) {
    __shared__ float cat[256];
    __shared__ float nxt[256];
    __shared__ float red[256];
    __shared__ float halfsum[256];
    int t = threadIdx.x;          // 256
    int lane = t & 31, w = t >> 5;
    {
        int col = t & 127, half = t >> 7;
        float s = 0.f;
#pragma unroll 4
        for (int i = 0; i < 128; ++i) s += part[(half * 128 + i) * DIM + col];
        halfsum[t] = s;
    }
    __syncthreads();
    if (t < 128) {
        cat[t + 128] = (halfsum[t] + halfsum[t + 128]) * (1.0f / NWORDS);
        cat[t]       = g_compound[t];
    }
    __syncthreads();
    for (int l = 0; l < 2; ++l) {
        const float* Wl = Wout + l * 256 * 256;
#pragma unroll 1
        for (int jj = 0; jj < 32; ++jj) {
            int j = w * 32 + jj;
            const float* row = Wl + j * 256;
            float s = 0.f;
#pragma unroll
            for (int i = 0; i < 8; ++i) s += cat[lane + i * 32] * row[lane + i * 32];
#pragma unroll
            for (int off = 16; off; off >>= 1) s += __shfl_xor_sync(0xffffffffu, s, off);
            if (lane == 0) {
                float v = s + bout[l * 256 + j];
                nxt[j] = v > 0.f ? v : 0.f;
            }
        }
        __syncthreads();
        cat[t] = nxt[t];
        __syncthreads();
    }
    red[t] = cat[t] * Wint[t];
    __syncthreads();
    for (int s = 128; s; s >>= 1) {
        if (t < s) red[t] += red[t + s];
        __syncthreads();
    }
    if (t == 0) out[0] = red[0] + bint[0];
}

// ------------------------- launch -------------------------
extern "C" void kernel_launch(void* const* d_in, const int* in_sizes, int n_in,
                              void* d_out, int out_size) {
    const int*   fingerprints = (const int*)d_in[0];
    const float* adjacency    = (const float*)d_in[1];
    const int*   words        = (const int*)d_in[2];
    const float* emb_fp       = (const float*)d_in[3];
    const float* emb_word     = (const float*)d_in[4];
    const float* W_gnn_w      = (const float*)d_in[5];
    const float* W_gnn_b      = (const float*)d_in[6];
    const float* conv_w       = (const float*)d_in[7];
    const float* conv_b       = (const float*)d_in[8];
    const float* W_att_w      = (const float*)d_in[9];
    const float* W_att_b      = (const float*)d_in[10];
    const float* W_out_w      = (const float*)d_in[11];
    const float* W_out_b      = (const float*)d_in[12];
    const float* W_int_w      = (const float*)d_in[13];
    const float* W_int_b      = (const float*)d_in[14];
    float* out = (float*)d_out;

    float *xs, *hs, *imgA, *imgB, *hsatt, *part;
    cudaGetSymbolAddress((void**)&xs,    g_xs);
    cudaGetSymbolAddress((void**)&hs,    g_hs);
    cudaGetSymbolAddress((void**)&imgA,  g_imgA);
    cudaGetSymbolAddress((void**)&imgB,  g_imgB);
    cudaGetSymbolAddress((void**)&hsatt, g_hsatt);
    cudaGetSymbolAddress((void**)&part,  g_part);

    int smem_lin = (64 * 129 + 16 * 256) * (int)sizeof(float);
    cudaFuncSetAttribute(linear_relu, cudaFuncAttributeMaxDynamicSharedMemorySize, smem_lin);

    static cudaStream_t s1 = 0, s3 = 0;
    static cudaEvent_t ef = 0, e1 = 0, e3 = 0;
    if (!s1) {
        int prLow = 0, prHigh = 0;
        cudaDeviceGetStreamPriorityRange(&prLow, &prHigh);
        cudaStreamCreateWithPriority(&s1, cudaStreamNonBlocking, prHigh);
        cudaStreamCreateWithPriority(&s3, cudaStreamNonBlocking, prLow);
        cudaEventCreateWithFlags(&ef, cudaEventDisableTiming);
        cudaEventCreateWithFlags(&e1, cudaEventDisableTiming);
        cudaEventCreateWithFlags(&e3, cudaEventDisableTiming);
    }

    // fork
    cudaEventRecord(ef, 0);
    cudaStreamWaitEvent(s1, ef, 0);
    cudaStreamWaitEvent(s3, ef, 0);

    dim3 cb(64, 2);
    dim3 linNW(NWORDS / 32, 2);

    // stream1 (high prio): conv chain, gather fused into conv1
    conv_leaky<<<NWORDS / 16, cb, 0, s1>>>(imgB, imgA, conv_w + 0 * CK * CK, conv_b + 0,
                                           words, emb_word);                               // #1
    // stream3 (low prio): GNN chain — occupancy-transparent kernels
    build_nz<<<NA / 8, 256, 0, s3>>>(adjacency);                                           // #2
    gnn_linear_light<<<NA / 16, 128, 0, s3>>>((const float*)0, W_gnn_w + 0, W_gnn_b + 0,
                                              hs, fingerprints, emb_fp, xs);               // #3
    spmm_add<<<NA / 8, 256, 0, s3>>>(hs);                                                  // #4
    gnn_linear_light<<<NA / 16, 128, 0, s3>>>(xs, W_gnn_w + 1 * DIM * DIM,
                                              W_gnn_b + 1 * DIM, hs,
                                              (const int*)0, (const float*)0, (float*)0);  // #5
    conv_leaky<<<NWORDS / 16, cb, 0, s1>>>(imgA, imgB, conv_w + 1 * CK * CK, conv_b + 1,
                                           (const int*)0, (const float*)0);                // #6 <- ncu (co-run!)
    spmm_add<<<NA / 8, 256, 0, s3>>>(hs);                                                  // #7
    gnn_linear_light<<<NA / 16, 128, 0, s3>>>(xs, W_gnn_w + 2 * DIM * DIM,
                                              W_gnn_b + 2 * DIM, hs,
                                              (const int*)0, (const float*)0, (float*)0);  // #8
    spmm_add<<<NA / 8, 256, 0, s3>>>(hs);                                                  // #9
    colsum_partial<<<32, 128, 0, s3>>>(xs, part, NA / 32);                                 // #10
    comb_att<<<1, 128, 0, s3>>>(part, W_att_w, W_att_b);                                   // #11
    cudaEventRecord(e3, s3);

    conv_leaky<<<NWORDS / 16, cb, 0, s1>>>(imgB, imgA, conv_w + 2 * CK * CK, conv_b + 2,
                                           (const int*)0, (const float*)0);                // #12
    linear_relu<<<linNW, 256, smem_lin, s1>>>(imgA, W_att_w, W_att_b, hsatt);              // #13

    // protein partials on s1 (needs hsatt from s1 + hatt from s3)
    cudaStreamWaitEvent(s1, e3, 0);
    protein_partial<<<NWORDS / 64, 128, 0, s1>>>(hsatt);                                   // #14
    cudaEventRecord(e1, s1);

    // join (e1 happens-after e3 via s1's wait)
    cudaStreamWaitEvent(0, e1, 0);
    final_mlp<<<1, 256>>>(part, W_out_w, W_out_b, W_int_w, W_int_b, out);                  // #15
}

// round 16
// speedup vs baseline: 1.2824x; 1.2824x over previous
#include <cuda_runtime.h>
#include <math.h>

#define NA     4096
#define NWORDS 16384
#define DIM    128
#define NZCAP  256
#define CK     23

// ------------------------- scratch (no allocations allowed) -------------------------
__device__ float g_xs[NA * DIM];
__device__ float g_hs[NA * DIM];
__device__ int   g_nzidx[NA * NZCAP];
__device__ int   g_nzcnt[NA];
__device__ float g_imgA[NWORDS * DIM];
__device__ float g_imgB[NWORDS * DIM];
__device__ float g_hsatt[NWORDS * DIM];
__device__ float g_part[256 * DIM];
__device__ float g_compound[DIM];
__device__ float g_hatt[DIM];

// ------------------------- f32x2 helpers -------------------------
typedef unsigned long long u64;
__device__ __forceinline__ void ffma2(u64& d, u64 a, u64 b) {
    asm("fma.rn.f32x2 %0, %1, %2, %0;" : "+l"(d) : "l"(a), "l"(b));
}
__device__ __forceinline__ u64 dup2(float w) {
    u64 r;
    asm("mov.b64 %0, {%1, %1};" : "=l"(r) : "r"(__float_as_uint(w)));
    return r;
}
__device__ __forceinline__ float lo32(u64 v) {
    return __uint_as_float((unsigned)(v & 0xffffffffull));
}
__device__ __forceinline__ float hi32(u64 v) {
    return __uint_as_float((unsigned)(v >> 32));
}

// ------------------------- sparse adjacency build (deterministic, ordered) -------------------------
__global__ void __launch_bounds__(256) build_nz(const float* __restrict__ adj) {
    int warp = (blockIdx.x * blockDim.x + threadIdx.x) >> 5;
    int lane = threadIdx.x & 31;
    if (warp >= NA) return;
    const float* row = adj + (size_t)warp * NA;
    int base = 0;
    for (int j0 = 0; j0 < NA; j0 += 32) {
        float v = row[j0 + lane];
        unsigned mask = __ballot_sync(0xffffffffu, v != 0.f);
        if (v != 0.f) {
            int r = __popc(mask & ((1u << lane) - 1));
            int p = base + r;
            if (p < NZCAP) g_nzidx[warp * NZCAP + p] = j0 + lane;
        }
        base += __popc(mask);
    }
    if (lane == 0) g_nzcnt[warp] = base < NZCAP ? base : NZCAP;
}

// ------------------------- Y = relu(X @ W^T + b), 32 rows x 64 cols, f32x2 (champion) -------------------------
__global__ void __launch_bounds__(256) linear_relu(const float* __restrict__ X,
                                                   const float* __restrict__ W,
                                                   const float* __restrict__ b,
                                                   float* __restrict__ Y,
                                                   const int* __restrict__ gidx,
                                                   const float* __restrict__ gemb,
                                                   float* __restrict__ Xout) {
    extern __shared__ float sm[];
    float*  sW  = sm;                         // [64][129]
    float2* sXP = (float2*)(sm + 64 * 129);   // [16][128] row pairs
    int tid = threadIdx.x;
    int jh  = blockIdx.y;                     // 0 or 1
    int r0  = blockIdx.x * 32;

    for (int idx = tid; idx < 64 * 128; idx += 256) {
        int j = idx >> 7, k = idx & 127;
        sW[j * 129 + k] = W[(size_t)(jh * 64 + j) * 128 + k];
    }
    for (int idx = tid; idx < 16 * 128; idx += 256) {
        int p = idx >> 7, k = idx & 127;
        int row0 = r0 + 2 * p;
        float x0, x1;
        if (gidx) {
            x0 = gemb[(size_t)gidx[row0] * DIM + k];
            x1 = gemb[(size_t)gidx[row0 + 1] * DIM + k];
            if (jh == 0) {
                Xout[(size_t)row0 * DIM + k]       = x0;
                Xout[(size_t)(row0 + 1) * DIM + k] = x1;
            }
        } else {
            x0 = X[(size_t)row0 * DIM + k];
            x1 = X[(size_t)(row0 + 1) * DIM + k];
        }
        sXP[p * 128 + k] = make_float2(x0, x1);
    }
    __syncthreads();

    int lane = tid & 31;
    int rg   = tid >> 5;
    int i0   = rg * 4;
    const u64* sxp = reinterpret_cast<const u64*>(sXP);
    const u64* pA  = sxp + (rg * 2) * 128;
    const u64* pB  = sxp + (rg * 2 + 1) * 128;

    u64 accA[2], accB[2];
#pragma unroll
    for (int q = 0; q < 2; ++q) { accA[q] = 0ull; accB[q] = 0ull; }

#pragma unroll 4
    for (int k = 0; k < 128; ++k) {
        u64 a01 = pA[k];
        u64 a23 = pB[k];
#pragma unroll
        for (int q = 0; q < 2; ++q) {
            u64 ww = dup2(sW[(lane + q * 32) * 129 + k]);
            ffma2(accA[q], a01, ww);
            ffma2(accB[q], a23, ww);
        }
    }
#pragma unroll
    for (int q = 0; q < 2; ++q) {
        int j = jh * 64 + lane + q * 32;
        float bj = b[j];
        float v0 = lo32(accA[q]) + bj;
        float v1 = hi32(accA[q]) + bj;
        float v2 = lo32(accB[q]) + bj;
        float v3 = hi32(accB[q]) + bj;
        Y[(size_t)(r0 + i0 + 0) * DIM + j] = v0 > 0.f ? v0 : 0.f;
        Y[(size_t)(r0 + i0 + 1) * DIM + j] = v1 > 0.f ? v1 : 0.f;
        Y[(size_t)(r0 + i0 + 2) * DIM + j] = v2 > 0.f ? v2 : 0.f;
        Y[(size_t)(r0 + i0 + 3) * DIM + j] = v3 > 0.f ? v3 : 0.f;
    }
}

// ------------------------- xs += A_sparse @ hs (warp-per-row, float4 lanes) -------------------------
__global__ void __launch_bounds__(256) spmm_add(const float* __restrict__ hs) {
    int row  = blockIdx.x * 8 + (threadIdx.x >> 5);
    int lane = threadIdx.x & 31;
    int cnt = g_nzcnt[row];
    const int* nz = g_nzidx + row * NZCAP;

    float4 a0 = make_float4(0.f, 0.f, 0.f, 0.f);
    float4 a1 = make_float4(0.f, 0.f, 0.f, 0.f);
    int t = 0;
    for (; t + 2 <= cnt; t += 2) {
        int j0 = nz[t], j1 = nz[t + 1];
        float4 v0 = *reinterpret_cast<const float4*>(hs + (size_t)j0 * DIM + lane * 4);
        float4 v1 = *reinterpret_cast<const float4*>(hs + (size_t)j1 * DIM + lane * 4);
        a0.x += v0.x; a0.y += v0.y; a0.z += v0.z; a0.w += v0.w;
        a1.x += v1.x; a1.y += v1.y; a1.z += v1.z; a1.w += v1.w;
    }
    if (t < cnt) {
        float4 v0 = *reinterpret_cast<const float4*>(hs + (size_t)nz[t] * DIM + lane * 4);
        a0.x += v0.x; a0.y += v0.y; a0.z += v0.z; a0.w += v0.w;
    }
    float4* dst = reinterpret_cast<float4*>(g_xs + (size_t)row * DIM + lane * 4);
    float4 x = *dst;
    x.x += a0.x + a1.x;
    x.y += a0.y + a1.y;
    x.z += a0.z + a1.z;
    x.w += a0.w + a1.w;
    *dst = x;
}

// ------------------------- column-sum partials -------------------------
__global__ void colsum_partial(const float* __restrict__ X, float* __restrict__ part,
                               int rows_per_block) {
    int c = threadIdx.x;
    int r0 = blockIdx.x * rows_per_block;
    float acc = 0.f;
    for (int r = 0; r < rows_per_block; ++r) acc += X[(size_t)(r0 + r) * DIM + c];
    part[blockIdx.x * DIM + c] = acc;
}

// ------------------------- 23x23 SAME conv + bias + leaky_relu -------------------------
// Proven 8-row body; smem trimmed to 28.0KB (SPITCH 87, scalar weight table)
// so 8 CTAs fit per SM (was 7) -> +14% resident warps for latency hiding.
#define SPITCH 87
#define TROWS  38   // 16 + 22 halo
__global__ void __launch_bounds__(128, 8) conv_leaky(const float* __restrict__ in,
                                                     float* __restrict__ out,
                                                     const float* __restrict__ kw,
                                                     const float* __restrict__ kb,
                                                     const int* __restrict__ widx,
                                                     const float* __restrict__ wemb) {
    __shared__ float2 s_in2[TROWS * SPITCH];
    __shared__ float  s_k[CK * CK];
    int tid = threadIdx.x + threadIdx.y * 64;
    int r0  = blockIdx.x * 16;

    for (int idx = tid; idx < TROWS * 86; idx += 128) {
        int rr = idx / 86;
        int qi = idx - rr * 86;
        int gr = r0 - 11 + rr;
        int q  = qi - 11;
        float lo = 0.f, hi = 0.f;
        if (gr >= 0 && gr < NWORDS) {
            const float* grow = widx ? (wemb + (size_t)widx[gr] * DIM)
                                     : (in + (size_t)gr * DIM);
            if (q >= 0)       lo = grow[q];
            if (q + 64 < 128) hi = grow[q + 64];
        }
        s_in2[rr * SPITCH + qi] = make_float2(lo, hi);
    }
    for (int idx = tid; idx < CK * CK; idx += 128) s_k[idx] = kw[idx];
    __syncthreads();

    float bias = kb[0];
    int cp    = threadIdx.x;
    int rbase = threadIdx.y * 8;

    u64 acc2[8];
#pragma unroll
    for (int o = 0; o < 8; ++o) acc2[o] = 0ull;

#pragma unroll 1
    for (int dc = 0; dc < CK; ++dc) {
        u64 wc2[CK];
#pragma unroll
        for (int dr = 0; dr < CK; ++dr)
            wc2[dr] = dup2(s_k[dr * CK + dc]);

        const u64* col = reinterpret_cast<const u64*>(s_in2) + rbase * SPITCH + cp + dc;
#pragma unroll
        for (int R = 0; R < 30; ++R) {
            u64 v2 = col[R * SPITCH];
#pragma unroll
            for (int dr = 0; dr < CK; ++dr) {
                int o = R - dr;
                if (o >= 0 && o < 8) ffma2(acc2[o], v2, wc2[dr]);
            }
        }
    }

#pragma unroll
    for (int o = 0; o < 8; ++o) {
        int row = r0 + rbase + o;
        float vl = lo32(acc2[o]) + bias;
        float vh = hi32(acc2[o]) + bias;
        out[(size_t)row * DIM + cp]      = vl > 0.f ? vl : 0.01f * vl;
        out[(size_t)row * DIM + cp + 64] = vh > 0.f ? vh : 0.01f * vh;
    }
}

// ------------------------- fused: GNN combine -> compound -> h_att -------------------------
__global__ void comb_att(const float* __restrict__ part, const float* __restrict__ W,
                         const float* __restrict__ b) {
    __shared__ float sc[DIM];
    int j = threadIdx.x;   // 128
    float acc = 0.f;
    for (int i = 0; i < 32; ++i) acc += part[i * DIM + j];
    float compv = acc * (1.0f / NA);
    g_compound[j] = compv;
    sc[j] = compv;
    __syncthreads();
    float h = b[j];
    for (int k = 0; k < 128; ++k) h += sc[k] * W[j * DIM + k];
    g_hatt[j] = h > 0.f ? h : 0.f;
}

// ------------------------- protein attention partials (grid 256, 64 rows/block) -------------------------
__global__ void protein_partial(const float* __restrict__ hs) {
    __shared__ float sh[DIM];
    __shared__ float sacc[4][DIM];
    int tid  = threadIdx.x;
    int lane = tid & 31;
    int w    = tid >> 5;
    sh[tid] = g_hatt[tid];
    __syncthreads();
    float h0 = sh[lane], h1 = sh[lane + 32], h2 = sh[lane + 64], h3 = sh[lane + 96];
    float a0 = 0.f, a1 = 0.f, a2 = 0.f, a3 = 0.f;
    int m0 = blockIdx.x * 64 + w * 16;
    for (int mi = 0; mi < 16; ++mi) {
        const float* row = hs + (size_t)(m0 + mi) * DIM;
        float d = row[lane] * h0 + row[lane + 32] * h1 + row[lane + 64] * h2 + row[lane + 96] * h3;
#pragma unroll
        for (int off = 16; off; off >>= 1) d += __shfl_xor_sync(0xffffffffu, d, off);
        float t = tanhf(d);
        float4 v = *reinterpret_cast<const float4*>(row + lane * 4);
        a0 += t * v.x;
        a1 += t * v.y;
        a2 += t * v.z;
        a3 += t * v.w;
    }
    sacc[w][lane * 4 + 0] = a0;
    sacc[w][lane * 4 + 1] = a1;
    sacc[w][lane * 4 + 2] = a2;
    sacc[w][lane * 4 + 3] = a3;
    __syncthreads();
    g_part[blockIdx.x * DIM + tid] =
        (sacc[0][tid] + sacc[1][tid]) + (sacc[2][tid] + sacc[3][tid]);
}

// ------------------------- fused: protein combine + 2-layer MLP + scalar head -------------------------
__global__ void final_mlp(const float* __restrict__ part,
                          const float* __restrict__ Wout, const float* __restrict__ bout,
                          const float* __restrict__ Wint, const float* __restrict__ bint,
                          float* __restrict__ out) {
    __shared__ float cat[256];
    __shared__ float nxt[256];
    __shared__ float red[256];
    __shared__ float halfsum[256];
    int t = threadIdx.x;          // 256
    int lane = t & 31, w = t >> 5;
    {
        int col = t & 127, half = t >> 7;
        float s = 0.f;
#pragma unroll 4
        for (int i = 0; i < 128; ++i) s += part[(half * 128 + i) * DIM + col];
        halfsum[t] = s;
    }
    __syncthreads();
    if (t < 128) {
        cat[t + 128] = (halfsum[t] + halfsum[t + 128]) * (1.0f / NWORDS);
        cat[t]       = g_compound[t];
    }
    __syncthreads();
    for (int l = 0; l < 2; ++l) {
        const float* Wl = Wout + l * 256 * 256;
#pragma unroll 1
        for (int jj = 0; jj < 32; ++jj) {
            int j = w * 32 + jj;
            const float* row = Wl + j * 256;
            float s = 0.f;
#pragma unroll
            for (int i = 0; i < 8; ++i) s += cat[lane + i * 32] * row[lane + i * 32];
#pragma unroll
            for (int off = 16; off; off >>= 1) s += __shfl_xor_sync(0xffffffffu, s, off);
            if (lane == 0) {
                float v = s + bout[l * 256 + j];
                nxt[j] = v > 0.f ? v : 0.f;
            }
        }
        __syncthreads();
        cat[t] = nxt[t];
        __syncthreads();
    }
    red[t] = cat[t] * Wint[t];
    __syncthreads();
    for (int s = 128; s; s >>= 1) {
        if (t < s) red[t] += red[t + s];
        __syncthreads();
    }
    if (t == 0) out[0] = red[0] + bint[0];
}

// ------------------------- launch (R9 champion schedule) -------------------------
extern "C" void kernel_launch(void* const* d_in, const int* in_sizes, int n_in,
                              void* d_out, int out_size) {
    const int*   fingerprints = (const int*)d_in[0];
    const float* adjacency    = (const float*)d_in[1];
    const int*   words        = (const int*)d_in[2];
    const float* emb_fp       = (const float*)d_in[3];
    const float* emb_word     = (const float*)d_in[4];
    const float* W_gnn_w      = (const float*)d_in[5];
    const float* W_gnn_b      = (const float*)d_in[6];
    const float* conv_w       = (const float*)d_in[7];
    const float* conv_b       = (const float*)d_in[8];
    const float* W_att_w      = (const float*)d_in[9];
    const float* W_att_b      = (const float*)d_in[10];
    const float* W_out_w      = (const float*)d_in[11];
    const float* W_out_b      = (const float*)d_in[12];
    const float* W_int_w      = (const float*)d_in[13];
    const float* W_int_b      = (const float*)d_in[14];
    float* out = (float*)d_out;

    float *xs, *hs, *imgA, *imgB, *hsatt, *part;
    cudaGetSymbolAddress((void**)&xs,    g_xs);
    cudaGetSymbolAddress((void**)&hs,    g_hs);
    cudaGetSymbolAddress((void**)&imgA,  g_imgA);
    cudaGetSymbolAddress((void**)&imgB,  g_imgB);
    cudaGetSymbolAddress((void**)&hsatt, g_hsatt);
    cudaGetSymbolAddress((void**)&part,  g_part);

    int smem_lin = (64 * 129 + 16 * 256) * (int)sizeof(float);
    cudaFuncSetAttribute(linear_relu, cudaFuncAttributeMaxDynamicSharedMemorySize, smem_lin);

    static cudaStream_t s1 = 0, s3 = 0;
    static cudaEvent_t ef = 0, e1 = 0, e3 = 0;
    if (!s1) {
        cudaStreamCreateWithFlags(&s1, cudaStreamNonBlocking);
        cudaStreamCreateWithFlags(&s3, cudaStreamNonBlocking);
        cudaEventCreateWithFlags(&ef, cudaEventDisableTiming);
        cudaEventCreateWithFlags(&e1, cudaEventDisableTiming);
        cudaEventCreateWithFlags(&e3, cudaEventDisableTiming);
    }

    // fork
    cudaEventRecord(ef, 0);
    cudaStreamWaitEvent(s1, ef, 0);
    cudaStreamWaitEvent(s3, ef, 0);

    dim3 cb(64, 2);
    dim3 linNA(NA / 32, 2), linNW(NWORDS / 32, 2);

    // stream1: conv chain (gather fused into conv1)
    conv_leaky<<<NWORDS / 16, cb, 0, s1>>>(imgB, imgA, conv_w + 0 * CK * CK, conv_b + 0,
                                           words, emb_word);                               // #1
    conv_leaky<<<NWORDS / 16, cb, 0, s1>>>(imgA, imgB, conv_w + 1 * CK * CK, conv_b + 1,
                                           (const int*)0, (const float*)0);                // #2
    // stream3: GNN chain
    build_nz<<<NA / 8, 256, 0, s3>>>(adjacency);                                           // #3
    linear_relu<<<linNA, 256, smem_lin, s3>>>((const float*)0, W_gnn_w + 0, W_gnn_b + 0,
                                              hs, fingerprints, emb_fp, xs);               // #4
    spmm_add<<<NA / 8, 256, 0, s3>>>(hs);                                                  // #5
    conv_leaky<<<NWORDS / 16, cb, 0, s1>>>(imgB, imgA, conv_w + 2 * CK * CK, conv_b + 2,
                                           (const int*)0, (const float*)0);                // #6 <- ncu
    linear_relu<<<linNW, 256, smem_lin, s1>>>(imgA, W_att_w, W_att_b, hsatt,
                                              (const int*)0, (const float*)0, (float*)0);
    for (int l = 1; l < 3; ++l) {
        linear_relu<<<linNA, 256, smem_lin, s3>>>(xs, W_gnn_w + l * DIM * DIM,
                                                  W_gnn_b + l * DIM, hs,
                                                  (const int*)0, (const float*)0, (float*)0);
        spmm_add<<<NA / 8, 256, 0, s3>>>(hs);
    }
    colsum_partial<<<32, 128, 0, s3>>>(xs, part, NA / 32);
    comb_att<<<1, 128, 0, s3>>>(part, W_att_w, W_att_b);

    // join
    cudaEventRecord(e1, s1);
    cudaEventRecord(e3, s3);
    cudaStreamWaitEvent(0, e1, 0);
    cudaStreamWaitEvent(0, e3, 0);

    // tail (legacy stream)
    protein_partial<<<NWORDS / 64, 128>>>(hsatt);
    final_mlp<<<1, 256>>>(part, W_out_w, W_out_b, W_int_w, W_int_b, out);
}

// round 17
// speedup vs baseline: 1.3024x; 1.0155x over previous
#include <cuda_runtime.h>
#include <math.h>

#define NA     4096
#define NWORDS 16384
#define DIM    128
#define NZCAP  256
#define CK     23

// ------------------------- scratch (no allocations allowed) -------------------------
__device__ float g_xs[NA * DIM];
__device__ float g_hs[NA * DIM];
__device__ int   g_nzidx[NA * NZCAP];
__device__ int   g_nzcnt[NA];
__device__ float g_imgA[NWORDS * DIM];
__device__ float g_imgB[NWORDS * DIM];
__device__ float g_hsatt[NWORDS * DIM];
__device__ float g_part[256 * DIM];
__device__ float g_compound[DIM];
__device__ float g_hatt[DIM];

// ------------------------- f32x2 helpers -------------------------
typedef unsigned long long u64;
__device__ __forceinline__ void ffma2(u64& d, u64 a, u64 b) {
    asm("fma.rn.f32x2 %0, %1, %2, %0;" : "+l"(d) : "l"(a), "l"(b));
}
__device__ __forceinline__ u64 dup2(float w) {
    u64 r;
    asm("mov.b64 %0, {%1, %1};" : "=l"(r) : "r"(__float_as_uint(w)));
    return r;
}
__device__ __forceinline__ float lo32(u64 v) {
    return __uint_as_float((unsigned)(v & 0xffffffffull));
}
__device__ __forceinline__ float hi32(u64 v) {
    return __uint_as_float((unsigned)(v >> 32));
}

// ------------------------- sparse adjacency build (deterministic, ordered) -------------------------
__global__ void __launch_bounds__(256) build_nz(const float* __restrict__ adj) {
    int warp = (blockIdx.x * blockDim.x + threadIdx.x) >> 5;
    int lane = threadIdx.x & 31;
    if (warp >= NA) return;
    const float* row = adj + (size_t)warp * NA;
    int base = 0;
    for (int j0 = 0; j0 < NA; j0 += 32) {
        float v = row[j0 + lane];
        unsigned mask = __ballot_sync(0xffffffffu, v != 0.f);
        if (v != 0.f) {
            int r = __popc(mask & ((1u << lane) - 1));
            int p = base + r;
            if (p < NZCAP) g_nzidx[warp * NZCAP + p] = j0 + lane;
        }
        base += __popc(mask);
    }
    if (lane == 0) g_nzcnt[warp] = base < NZCAP ? base : NZCAP;
}

// ------------------------- Y = relu(X @ W^T + b), 32 rows x 64 cols, f32x2 (attlin) -------------------------
__global__ void __launch_bounds__(256) linear_relu(const float* __restrict__ X,
                                                   const float* __restrict__ W,
                                                   const float* __restrict__ b,
                                                   float* __restrict__ Y) {
    extern __shared__ float sm[];
    float*  sW  = sm;                         // [64][129]
    float2* sXP = (float2*)(sm + 64 * 129);   // [16][128] row pairs
    int tid = threadIdx.x;
    int jh  = blockIdx.y;
    int r0  = blockIdx.x * 32;

    for (int idx = tid; idx < 64 * 128; idx += 256) {
        int j = idx >> 7, k = idx & 127;
        sW[j * 129 + k] = W[(size_t)(jh * 64 + j) * 128 + k];
    }
    for (int idx = tid; idx < 16 * 128; idx += 256) {
        int p = idx >> 7, k = idx & 127;
        int row0 = r0 + 2 * p;
        sXP[p * 128 + k] = make_float2(X[(size_t)row0 * DIM + k],
                                       X[(size_t)(row0 + 1) * DIM + k]);
    }
    __syncthreads();

    int lane = tid & 31;
    int rg   = tid >> 5;
    int i0   = rg * 4;
    const u64* sxp = reinterpret_cast<const u64*>(sXP);
    const u64* pA  = sxp + (rg * 2) * 128;
    const u64* pB  = sxp + (rg * 2 + 1) * 128;

    u64 accA[2], accB[2];
#pragma unroll
    for (int q = 0; q < 2; ++q) { accA[q] = 0ull; accB[q] = 0ull; }

#pragma unroll 4
    for (int k = 0; k < 128; ++k) {
        u64 a01 = pA[k];
        u64 a23 = pB[k];
#pragma unroll
        for (int q = 0; q < 2; ++q) {
            u64 ww = dup2(sW[(lane + q * 32) * 129 + k]);
            ffma2(accA[q], a01, ww);
            ffma2(accB[q], a23, ww);
        }
    }
#pragma unroll
    for (int q = 0; q < 2; ++q) {
        int j = jh * 64 + lane + q * 32;
        float bj = b[j];
        float v0 = lo32(accA[q]) + bj;
        float v1 = hi32(accA[q]) + bj;
        float v2 = lo32(accB[q]) + bj;
        float v3 = hi32(accB[q]) + bj;
        Y[(size_t)(r0 + i0 + 0) * DIM + j] = v0 > 0.f ? v0 : 0.f;
        Y[(size_t)(r0 + i0 + 1) * DIM + j] = v1 > 0.f ? v1 : 0.f;
        Y[(size_t)(r0 + i0 + 2) * DIM + j] = v2 > 0.f ? v2 : 0.f;
        Y[(size_t)(r0 + i0 + 3) * DIM + j] = v3 > 0.f ? v3 : 0.f;
    }
}

// ------------------------- GNN linear: 16 rows x 64 cols (lower latency per block) -------------------------
// Same per-output k-order as linear_relu -> bitwise identical results.
__global__ void __launch_bounds__(256) linear_relu16(const float* __restrict__ X,
                                                     const float* __restrict__ W,
                                                     const float* __restrict__ b,
                                                     float* __restrict__ Y,
                                                     const int* __restrict__ gidx,
                                                     const float* __restrict__ gemb,
                                                     float* __restrict__ Xout) {
    extern __shared__ float sm[];
    float*  sW  = sm;                         // [64][129]
    float2* sXP = (float2*)(sm + 64 * 129);   // [8][128] row pairs
    int tid = threadIdx.x;
    int jh  = blockIdx.y;                     // 0 or 1
    int r0  = blockIdx.x * 16;

    for (int idx = tid; idx < 64 * 128; idx += 256) {
        int j = idx >> 7, k = idx & 127;
        sW[j * 129 + k] = W[(size_t)(jh * 64 + j) * 128 + k];
    }
    for (int idx = tid; idx < 8 * 128; idx += 256) {
        int p = idx >> 7, k = idx & 127;
        int row0 = r0 + 2 * p;
        float x0, x1;
        if (gidx) {
            x0 = gemb[(size_t)gidx[row0] * DIM + k];
            x1 = gemb[(size_t)gidx[row0 + 1] * DIM + k];
            if (jh == 0) {
                Xout[(size_t)row0 * DIM + k]       = x0;
                Xout[(size_t)(row0 + 1) * DIM + k] = x1;
            }
        } else {
            x0 = X[(size_t)row0 * DIM + k];
            x1 = X[(size_t)(row0 + 1) * DIM + k];
        }
        sXP[p * 128 + k] = make_float2(x0, x1);
    }
    __syncthreads();

    int lane = tid & 31;
    int rg   = tid >> 5;        // warp-uniform, 0..7 -> row pair rg
    const u64* pA = reinterpret_cast<const u64*>(sXP) + rg * 128;

    u64 accA[2];
    accA[0] = 0ull; accA[1] = 0ull;

#pragma unroll 4
    for (int k = 0; k < 128; ++k) {
        u64 a01 = pA[k];
#pragma unroll
        for (int q = 0; q < 2; ++q) {
            u64 ww = dup2(sW[(lane + q * 32) * 129 + k]);
            ffma2(accA[q], a01, ww);
        }
    }
#pragma unroll
    for (int q = 0; q < 2; ++q) {
        int j = jh * 64 + lane + q * 32;
        float bj = b[j];
        float v0 = lo32(accA[q]) + bj;
        float v1 = hi32(accA[q]) + bj;
        Y[(size_t)(r0 + rg * 2 + 0) * DIM + j] = v0 > 0.f ? v0 : 0.f;
        Y[(size_t)(r0 + rg * 2 + 1) * DIM + j] = v1 > 0.f ? v1 : 0.f;
    }
}

// ------------------------- xs += A_sparse @ hs (warp-per-row, float4 lanes) -------------------------
__global__ void __launch_bounds__(256) spmm_add(const float* __restrict__ hs) {
    int row  = blockIdx.x * 8 + (threadIdx.x >> 5);
    int lane = threadIdx.x & 31;
    int cnt = g_nzcnt[row];
    const int* nz = g_nzidx + row * NZCAP;

    float4 a0 = make_float4(0.f, 0.f, 0.f, 0.f);
    float4 a1 = make_float4(0.f, 0.f, 0.f, 0.f);
    int t = 0;
    for (; t + 2 <= cnt; t += 2) {
        int j0 = nz[t], j1 = nz[t + 1];
        float4 v0 = *reinterpret_cast<const float4*>(hs + (size_t)j0 * DIM + lane * 4);
        float4 v1 = *reinterpret_cast<const float4*>(hs + (size_t)j1 * DIM + lane * 4);
        a0.x += v0.x; a0.y += v0.y; a0.z += v0.z; a0.w += v0.w;
        a1.x += v1.x; a1.y += v1.y; a1.z += v1.z; a1.w += v1.w;
    }
    if (t < cnt) {
        float4 v0 = *reinterpret_cast<const float4*>(hs + (size_t)nz[t] * DIM + lane * 4);
        a0.x += v0.x; a0.y += v0.y; a0.z += v0.z; a0.w += v0.w;
    }
    float4* dst = reinterpret_cast<float4*>(g_xs + (size_t)row * DIM + lane * 4);
    float4 x = *dst;
    x.x += a0.x + a1.x;
    x.y += a0.y + a1.y;
    x.z += a0.z + a1.z;
    x.w += a0.w + a1.w;
    *dst = x;
}

// ------------------------- column-sum partials -------------------------
__global__ void colsum_partial(const float* __restrict__ X, float* __restrict__ part,
                               int rows_per_block) {
    int c = threadIdx.x;
    int r0 = blockIdx.x * rows_per_block;
    float acc = 0.f;
    for (int r = 0; r < rows_per_block; ++r) acc += X[(size_t)(r0 + r) * DIM + c];
    part[blockIdx.x * DIM + c] = acc;
}

// ------------------------- 23x23 SAME conv + bias + leaky_relu (28KB smem, 8 CTAs/SM) -------------------------
#define SPITCH 87
#define TROWS  38   // 16 + 22 halo
__global__ void __launch_bounds__(128, 8) conv_leaky(const float* __restrict__ in,
                                                     float* __restrict__ out,
                                                     const float* __restrict__ kw,
                                                     const float* __restrict__ kb,
                                                     const int* __restrict__ widx,
                                                     const float* __restrict__ wemb) {
    __shared__ float2 s_in2[TROWS * SPITCH];
    __shared__ float  s_k[CK * CK];
    int tid = threadIdx.x + threadIdx.y * 64;
    int r0  = blockIdx.x * 16;

    for (int idx = tid; idx < TROWS * 86; idx += 128) {
        int rr = idx / 86;
        int qi = idx - rr * 86;
        int gr = r0 - 11 + rr;
        int q  = qi - 11;
        float lo = 0.f, hi = 0.f;
        if (gr >= 0 && gr < NWORDS) {
            const float* grow = widx ? (wemb + (size_t)widx[gr] * DIM)
                                     : (in + (size_t)gr * DIM);
            if (q >= 0)       lo = grow[q];
            if (q + 64 < 128) hi = grow[q + 64];
        }
        s_in2[rr * SPITCH + qi] = make_float2(lo, hi);
    }
    for (int idx = tid; idx < CK * CK; idx += 128) s_k[idx] = kw[idx];
    __syncthreads();

    float bias = kb[0];
    int cp    = threadIdx.x;
    int rbase = threadIdx.y * 8;

    u64 acc2[8];
#pragma unroll
    for (int o = 0; o < 8; ++o) acc2[o] = 0ull;

#pragma unroll 1
    for (int dc = 0; dc < CK; ++dc) {
        u64 wc2[CK];
#pragma unroll
        for (int dr = 0; dr < CK; ++dr)
            wc2[dr] = dup2(s_k[dr * CK + dc]);

        const u64* col = reinterpret_cast<const u64*>(s_in2) + rbase * SPITCH + cp + dc;
#pragma unroll
        for (int R = 0; R < 30; ++R) {
            u64 v2 = col[R * SPITCH];
#pragma unroll
            for (int dr = 0; dr < CK; ++dr) {
                int o = R - dr;
                if (o >= 0 && o < 8) ffma2(acc2[o], v2, wc2[dr]);
            }
        }
    }

#pragma unroll
    for (int o = 0; o < 8; ++o) {
        int row = r0 + rbase + o;
        float vl = lo32(acc2[o]) + bias;
        float vh = hi32(acc2[o]) + bias;
        out[(size_t)row * DIM + cp]      = vl > 0.f ? vl : 0.01f * vl;
        out[(size_t)row * DIM + cp + 64] = vh > 0.f ? vh : 0.01f * vh;
    }
}

// ------------------------- fused: GNN combine -> compound -> h_att -------------------------
__global__ void comb_att(const float* __restrict__ part, const float* __restrict__ W,
                         const float* __restrict__ b) {
    __shared__ float sc[DIM];
    int j = threadIdx.x;   // 128
    float acc = 0.f;
    for (int i = 0; i < 32; ++i) acc += part[i * DIM + j];
    float compv = acc * (1.0f / NA);
    g_compound[j] = compv;
    sc[j] = compv;
    __syncthreads();
    float h = b[j];
    for (int k = 0; k < 128; ++k) h += sc[k] * W[j * DIM + k];
    g_hatt[j] = h > 0.f ? h : 0.f;
}

// ------------------------- protein attention partials (grid 256, 64 rows/block) -------------------------
__global__ void protein_partial(const float* __restrict__ hs) {
    __shared__ float sh[DIM];
    __shared__ float sacc[4][DIM];
    int tid  = threadIdx.x;
    int lane = tid & 31;
    int w    = tid >> 5;
    sh[tid] = g_hatt[tid];
    __syncthreads();
    float h0 = sh[lane], h1 = sh[lane + 32], h2 = sh[lane + 64], h3 = sh[lane + 96];
    float a0 = 0.f, a1 = 0.f, a2 = 0.f, a3 = 0.f;
    int m0 = blockIdx.x * 64 + w * 16;
    for (int mi = 0; mi < 16; ++mi) {
        const float* row = hs + (size_t)(m0 + mi) * DIM;
        float d = row[lane] * h0 + row[lane + 32] * h1 + row[lane + 64] * h2 + row[lane + 96] * h3;
#pragma unroll
        for (int off = 16; off; off >>= 1) d += __shfl_xor_sync(0xffffffffu, d, off);
        float t = tanhf(d);
        float4 v = *reinterpret_cast<const float4*>(row + lane * 4);
        a0 += t * v.x;
        a1 += t * v.y;
        a2 += t * v.z;
        a3 += t * v.w;
    }
    sacc[w][lane * 4 + 0] = a0;
    sacc[w][lane * 4 + 1] = a1;
    sacc[w][lane * 4 + 2] = a2;
    sacc[w][lane * 4 + 3] = a3;
    __syncthreads();
    g_part[blockIdx.x * DIM + tid] =
        (sacc[0][tid] + sacc[1][tid]) + (sacc[2][tid] + sacc[3][tid]);
}

// ------------------------- fused: protein combine + 2-layer MLP + scalar head -------------------------
__global__ void final_mlp(const float* __restrict__ part,
                          const float* __restrict__ Wout, const float* __restrict__ bout,
                          const float* __restrict__ Wint, const float* __restrict__ bint,
                          float* __restrict__ out) {
    __shared__ float cat[256];
    __shared__ float nxt[256];
    __shared__ float red[256];
    __shared__ float halfsum[256];
    int t = threadIdx.x;          // 256
    int lane = t & 31, w = t >> 5;
    {
        int col = t & 127, half = t >> 7;
        float s = 0.f;
#pragma unroll 4
        for (int i = 0; i < 128; ++i) s += part[(half * 128 + i) * DIM + col];
        halfsum[t] = s;
    }
    __syncthreads();
    if (t < 128) {
        cat[t + 128] = (halfsum[t] + halfsum[t + 128]) * (1.0f / NWORDS);
        cat[t]       = g_compound[t];
    }
    __syncthreads();
    for (int l = 0; l < 2; ++l) {
        const float* Wl = Wout + l * 256 * 256;
#pragma unroll 1
        for (int jj = 0; jj < 32; ++jj) {
            int j = w * 32 + jj;
            const float* row = Wl + j * 256;
            float s = 0.f;
#pragma unroll
            for (int i = 0; i < 8; ++i) s += cat[lane + i * 32] * row[lane + i * 32];
#pragma unroll
            for (int off = 16; off; off >>= 1) s += __shfl_xor_sync(0xffffffffu, s, off);
            if (lane == 0) {
                float v = s + bout[l * 256 + j];
                nxt[j] = v > 0.f ? v : 0.f;
            }
        }
        __syncthreads();
        cat[t] = nxt[t];
        __syncthreads();
    }
    red[t] = cat[t] * Wint[t];
    __syncthreads();
    for (int s = 128; s; s >>= 1) {
        if (t < s) red[t] += red[t + s];
        __syncthreads();
    }
    if (t == 0) out[0] = red[0] + bint[0];
}

// ------------------------- launch -------------------------
extern "C" void kernel_launch(void* const* d_in, const int* in_sizes, int n_in,
                              void* d_out, int out_size) {
    const int*   fingerprints = (const int*)d_in[0];
    const float* adjacency    = (const float*)d_in[1];
    const int*   words        = (const int*)d_in[2];
    const float* emb_fp       = (const float*)d_in[3];
    const float* emb_word     = (const float*)d_in[4];
    const float* W_gnn_w      = (const float*)d_in[5];
    const float* W_gnn_b      = (const float*)d_in[6];
    const float* conv_w       = (const float*)d_in[7];
    const float* conv_b       = (const float*)d_in[8];
    const float* W_att_w      = (const float*)d_in[9];
    const float* W_att_b      = (const float*)d_in[10];
    const float* W_out_w      = (const float*)d_in[11];
    const float* W_out_b      = (const float*)d_in[12];
    const float* W_int_w      = (const float*)d_in[13];
    const float* W_int_b      = (const float*)d_in[14];
    float* out = (float*)d_out;

    float *xs, *hs, *imgA, *imgB, *hsatt, *part;
    cudaGetSymbolAddress((void**)&xs,    g_xs);
    cudaGetSymbolAddress((void**)&hs,    g_hs);
    cudaGetSymbolAddress((void**)&imgA,  g_imgA);
    cudaGetSymbolAddress((void**)&imgB,  g_imgB);
    cudaGetSymbolAddress((void**)&hsatt, g_hsatt);
    cudaGetSymbolAddress((void**)&part,  g_part);

    int smem_lin   = (64 * 129 + 16 * 256) * (int)sizeof(float);
    int smem_lin16 = (64 * 129 + 8 * 256) * (int)sizeof(float);
    cudaFuncSetAttribute(linear_relu, cudaFuncAttributeMaxDynamicSharedMemorySize, smem_lin);
    cudaFuncSetAttribute(linear_relu16, cudaFuncAttributeMaxDynamicSharedMemorySize, smem_lin16);

    static cudaStream_t s1 = 0, s2 = 0, s3 = 0;
    static cudaEvent_t ef = 0, e1 = 0, e2 = 0, e3 = 0;
    if (!s1) {
        cudaStreamCreateWithFlags(&s1, cudaStreamNonBlocking);
        cudaStreamCreateWithFlags(&s2, cudaStreamNonBlocking);
        cudaStreamCreateWithFlags(&s3, cudaStreamNonBlocking);
        cudaEventCreateWithFlags(&ef, cudaEventDisableTiming);
        cudaEventCreateWithFlags(&e1, cudaEventDisableTiming);
        cudaEventCreateWithFlags(&e2, cudaEventDisableTiming);
        cudaEventCreateWithFlags(&e3, cudaEventDisableTiming);
    }

    // fork
    cudaEventRecord(ef, 0);
    cudaStreamWaitEvent(s1, ef, 0);
    cudaStreamWaitEvent(s2, ef, 0);
    cudaStreamWaitEvent(s3, ef, 0);

    dim3 cb(64, 2);
    dim3 linNA(NA / 16, 2), linNW(NWORDS / 32, 2);

    // stream1: conv chain (gather fused into conv1)
    conv_leaky<<<NWORDS / 16, cb, 0, s1>>>(imgB, imgA, conv_w + 0 * CK * CK, conv_b + 0,
                                           words, emb_word);
    // stream2: adjacency CSR build (independent of lin0)
    build_nz<<<NA / 8, 256, 0, s2>>>(adjacency);
    cudaEventRecord(e2, s2);
    // stream3: GNN layer-0 linear (inline fingerprint gather), parallel with build_nz
    linear_relu16<<<linNA, 256, smem_lin16, s3>>>((const float*)0, W_gnn_w + 0, W_gnn_b + 0,
                                                  hs, fingerprints, emb_fp, xs);
    cudaStreamWaitEvent(s3, e2, 0);
    spmm_add<<<NA / 8, 256, 0, s3>>>(hs);

    conv_leaky<<<NWORDS / 16, cb, 0, s1>>>(imgA, imgB, conv_w + 1 * CK * CK, conv_b + 1,
                                           (const int*)0, (const float*)0);

    for (int l = 1; l < 3; ++l) {
        linear_relu16<<<linNA, 256, smem_lin16, s3>>>(xs, W_gnn_w + l * DIM * DIM,
                                                      W_gnn_b + l * DIM, hs,
                                                      (const int*)0, (const float*)0, (float*)0);
        spmm_add<<<NA / 8, 256, 0, s3>>>(hs);
    }
    colsum_partial<<<32, 128, 0, s3>>>(xs, part, NA / 32);
    comb_att<<<1, 128, 0, s3>>>(part, W_att_w, W_att_b);
    cudaEventRecord(e3, s3);

    conv_leaky<<<NWORDS / 16, cb, 0, s1>>>(imgB, imgA, conv_w + 2 * CK * CK, conv_b + 2,
                                           (const int*)0, (const float*)0);
    linear_relu<<<linNW, 256, smem_lin, s1>>>(imgA, W_att_w, W_att_b, hsatt);

    // protein partials on s1 (needs hsatt from s1 + hatt from s3; e3 long done)
    cudaStreamWaitEvent(s1, e3, 0);
    protein_partial<<<NWORDS / 64, 128, 0, s1>>>(hsatt);
    cudaEventRecord(e1, s1);

    // join (e1 happens-after e3 via s1's wait)
    cudaStreamWaitEvent(0, e1, 0);
    final_mlp<<<1, 256>>>(part, W_out_w, W_out_b, W_int_w, W_int_b, out);
}